// round 9
// baseline (speedup 1.0000x reference)
#include <cuda_runtime.h>
#include <cuda_fp16.h>
#include <cstdint>

#define H0 200
#define W0 304
#define H1 100
#define W1 152
#define H2 50
#define W2 76
#define HW0 (H0*W0)
#define C_TOT 768

// Fused HWC fp16 map, 16B-aligned: [H0*W0][96 octets of 8ch]
__device__ uint4 g_fused[(size_t)HW0 * (C_TOT/8)];

// ---------------------------------------------------------------------------
// Unified prep kernel: one launch, three regions run concurrently.
//  region 0 (8000 blocks): transpose feat0 -> ch [0,256)
//  region 1 (2000 blocks): 2x upsample feat1 -> ch [256,512)
//  region 2 (1200 blocks): 4x upsample feat2 -> ch [512,768)
// Interleave 20:5:3 per 28 blocks so all regions are active in every wave.
// ---------------------------------------------------------------------------
#define P1_PAD 65
#define P2_PAD 65
#define PREP_BLOCKS (8000 + 2000 + 1200)

__global__ __launch_bounds__(256) void prep_all(
    const float* __restrict__ f0,
    const float* __restrict__ f1,
    const float* __restrict__ f2)
{
    __shared__ char smem_u[2 * 128 * P2_PAD * 2];   // 33280B union
    int warp = threadIdx.x >> 5, lane = threadIdx.x & 31;
    __half* gf = (__half*)g_fused;

    int gq = blockIdx.x / 28, r = blockIdx.x % 28;
    if (r < 20) {
        // ---------------- region 0: transpose feat0 ----------------
        int idx = gq * 20 + r;
        int xi = idx % 10; int t = idx / 10;
        int y = t % 200;   int g = t / 200;
        int xblk = xi * 32;
        int x = xblk + lane;
        int c0 = g * 64;
        float (*tile)[33] = (float(*)[33])smem_u;
        if (x < W0) {
            const float* src = f0 + (size_t)c0 * HW0 + y * W0 + x;
#pragma unroll
            for (int p = 0; p < 8; p++) {
                int cl = warp * 8 + p;
                tile[cl][lane] = __ldg(src + (size_t)cl * HW0);
            }
        }
        __syncthreads();
#pragma unroll
        for (int q = 0; q < 4; q++) {
            int px = warp * 4 + q, xg = xblk + px;
            if (xg < W0) {
                __half2 v = __floats2half2_rn(tile[2 * lane][px], tile[2 * lane + 1][px]);
                *(__half2*)(gf + (size_t)(y * W0 + xg) * C_TOT + c0 + 2 * lane) = v;
            }
        }
    } else if (r < 25) {
        // ---------------- region 1: 2x upsample feat1 ----------------
        int idx = gq * 5 + (r - 20);
        int xi = idx % 5; int t = idx / 5;
        int Y = t % 100;  int cb = (t / 100) * 64;
        int xb = xi * 64;
        __half* tile = (__half*)smem_u;     // [2*64][P1_PAD]
        int j  = xb / 2 + lane;
        int xm = max(j - 1, 0), xc = min(j, W1 - 1), xp = min(j + 1, W1 - 1);
        int r0 = max(Y - 1, 0), r1 = Y, r2 = min(Y + 1, H1 - 1);
#pragma unroll
        for (int p = 0; p < 8; p++) {
            int cl = warp * 8 + p;
            const float* pl = f1 + (size_t)(cb + cl) * (H1 * W1);
            float v00 = __ldg(pl + r0 * W1 + xm), v01 = __ldg(pl + r0 * W1 + xc), v02 = __ldg(pl + r0 * W1 + xp);
            float v10 = __ldg(pl + r1 * W1 + xm), v11 = __ldg(pl + r1 * W1 + xc), v12 = __ldg(pl + r1 * W1 + xp);
            float v20 = __ldg(pl + r2 * W1 + xm), v21 = __ldg(pl + r2 * W1 + xc), v22 = __ldg(pl + r2 * W1 + xp);
            float a0 = 0.25f * v00 + 0.75f * v01, b0 = 0.75f * v01 + 0.25f * v02;
            float a1 = 0.25f * v10 + 0.75f * v11, b1 = 0.75f * v11 + 0.25f * v12;
            float a2 = 0.25f * v20 + 0.75f * v21, b2 = 0.75f * v21 + 0.25f * v22;
            float e0 = 0.25f * a0 + 0.75f * a1, o0 = 0.25f * b0 + 0.75f * b1;
            float e1 = 0.75f * a1 + 0.25f * a2, o1 = 0.75f * b1 + 0.25f * b2;
            int px = 2 * lane;
            tile[(0 * 64 + px)     * P1_PAD + cl] = __float2half_rn(e0);
            tile[(0 * 64 + px + 1) * P1_PAD + cl] = __float2half_rn(o0);
            tile[(1 * 64 + px)     * P1_PAD + cl] = __float2half_rn(e1);
            tile[(1 * 64 + px + 1) * P1_PAD + cl] = __float2half_rn(o1);
        }
        __syncthreads();
        for (int i = warp; i < 128; i += 8) {
            int row = i >> 6, px = i & 63;
            int xg = xb + px;
            if (xg < W0) {
                __half lo = tile[(row * 64 + px) * P1_PAD + 2 * lane];
                __half hi = tile[(row * 64 + px) * P1_PAD + 2 * lane + 1];
                *(__half2*)(gf + (size_t)((2 * Y + row) * W0 + xg) * C_TOT + 256 + cb + 2 * lane)
                    = __halves2half2(lo, hi);
            }
        }
    } else {
        // ---------------- region 2: 4x upsample feat2 ----------------
        int idx = gq * 3 + (r - 25);
        int xi = idx % 3; int t = idx / 3;
        int yb = t % 100; int cb = (t / 100) * 64;
        int xb = xi * 128;
        __half* tile = (__half*)smem_u;     // [2*128][P2_PAD]
        int Y = yb >> 1, half = yb & 1;
        int j  = xb / 4 + lane;
        int xm = max(j - 1, 0), xc = min(j, W2 - 1), xp = min(j + 1, W2 - 1);
        int ra = half ? Y : max(Y - 1, 0);
        int rb = half ? min(Y + 1, H2 - 1) : Y;
        float wya0, wyb0, wya1, wyb1;
        if (half == 0) { wya0 = 0.375f; wyb0 = 0.625f; wya1 = 0.125f; wyb1 = 0.875f; }
        else           { wya0 = 0.875f; wyb0 = 0.125f; wya1 = 0.625f; wyb1 = 0.375f; }
#pragma unroll
        for (int p = 0; p < 8; p++) {
            int cl = warp * 8 + p;
            const float* pl = f2 + (size_t)(cb + cl) * (H2 * W2);
            float va0 = __ldg(pl + ra * W2 + xm), va1 = __ldg(pl + ra * W2 + xc), va2 = __ldg(pl + ra * W2 + xp);
            float vb0 = __ldg(pl + rb * W2 + xm), vb1 = __ldg(pl + rb * W2 + xc), vb2 = __ldg(pl + rb * W2 + xp);
            float qa[4], qb[4];
            qa[0] = 0.375f * va0 + 0.625f * va1; qa[1] = 0.125f * va0 + 0.875f * va1;
            qa[2] = 0.875f * va1 + 0.125f * va2; qa[3] = 0.625f * va1 + 0.375f * va2;
            qb[0] = 0.375f * vb0 + 0.625f * vb1; qb[1] = 0.125f * vb0 + 0.875f * vb1;
            qb[2] = 0.875f * vb1 + 0.125f * vb2; qb[3] = 0.625f * vb1 + 0.375f * vb2;
            int px = 4 * lane;
#pragma unroll
            for (int q = 0; q < 4; q++) {
                float o0 = wya0 * qa[q] + wyb0 * qb[q];
                float o1 = wya1 * qa[q] + wyb1 * qb[q];
                tile[(0 * 128 + px + q) * P2_PAD + cl] = __float2half_rn(o0);
                tile[(1 * 128 + px + q) * P2_PAD + cl] = __float2half_rn(o1);
            }
        }
        __syncthreads();
        int ybase = 4 * Y + 2 * half;
        for (int i = warp; i < 256; i += 8) {
            int row = i >> 7, px = i & 127;
            int xg = xb + px;
            if (xg < W0) {
                __half lo = tile[(row * 128 + px) * P2_PAD + 2 * lane];
                __half hi = tile[(row * 128 + px) * P2_PAD + 2 * lane + 1];
                *(__half2*)(gf + (size_t)((ybase + row) * W0 + xg) * C_TOT + 512 + cb + 2 * lane)
                    = __halves2half2(lo, hi);
            }
        }
    }
}

// ---------------------------------------------------------------------------
// RoIAlign: grid (N, 7 oh), block 96; thread = one 8-channel octet (uint4).
// Taps accumulated in half2 via HFMA2 (two 8-tap trees + hadd2 combine).
// x/y coordinate tables in smem; 0.25 bin-average folded into y weights.
// Outputs staged packed (STS.128), then semi-coalesced fp32 global store.
// ---------------------------------------------------------------------------
#define OPP 96   // uint4 octets per pixel

#define TAP(xo, ux, yo, wy, A) { \
    uint4 v = __ldg(fp + (yo) + (xo)); \
    __half2 kh = __float2half2_rn((wy) * (ux)); \
    A[0] = __hfma2(kh, *(__half2*)&v.x, A[0]); \
    A[1] = __hfma2(kh, *(__half2*)&v.y, A[1]); \
    A[2] = __hfma2(kh, *(__half2*)&v.z, A[2]); \
    A[3] = __hfma2(kh, *(__half2*)&v.w, A[3]); }

__global__ __launch_bounds__(96, 8) void roi_kernel(
    const float* __restrict__ boxes,
    const int*   __restrict__ img_h,
    const int*   __restrict__ img_w,
    float* __restrict__ out)
{
    int roi = blockIdx.x;
    int oh  = blockIdx.y;
    int tid = threadIdx.x;          // octet index 0..95

    __shared__ int   sxo[14][2];    // x corner offsets (uint4 units)
    __shared__ float swx[14][2];
    __shared__ int   syo[2][2];     // y corner offsets (uint4 units)
    __shared__ float swy[2][2];     // scaled by 0.25
    __shared__ uint4 s_out4[7 * 96];

    if (tid < 16) {
        bool isx = tid < 14;
        int  s, bin;
        if (isx) { s = tid;      bin = s >> 1; }
        else     { s = tid - 14; bin = oh;     }
        float offs = 0.25f + 0.5f * (float)(isx ? (s & 1) : s);

        float scale = isx ? ((float)W0 / (float)__ldg(img_w))
                          : ((float)H0 / (float)__ldg(img_h));
        float p1 = __ldg(boxes + roi * 4 + (isx ? 0 : 1)) * scale;
        float p2 = __ldg(boxes + roi * 4 + (isx ? 2 : 3)) * scale;
        float bs = fmaxf(p2 - p1, 1.0f) * (1.0f / 7.0f);
        float P  = p1 + ((float)bin + offs) * bs;

        int lim = isx ? W0 : H0;
        bool valid = (P >= -1.0f) && (P <= (float)lim);
        float Pc = fminf(fmaxf(P, 0.0f), (float)(lim - 1));
        int p0  = (int)Pc;
        int p1i = min(p0 + 1, lim - 1);
        float l  = Pc - (float)p0;
        float w0 = valid ? (1.0f - l) : 0.0f;
        float w1 = valid ? l : 0.0f;

        if (isx) {
            sxo[s][0] = p0 * OPP;    sxo[s][1] = p1i * OPP;
            swx[s][0] = w0;          swx[s][1] = w1;
        } else {
            syo[s][0] = p0 * (W0 * OPP);   syo[s][1] = p1i * (W0 * OPP);
            swy[s][0] = w0 * 0.25f;        swy[s][1] = w1 * 0.25f;
        }
    }
    __syncthreads();

    const uint4* fp = g_fused + tid;

    int   ya0 = syo[0][0], ya1 = syo[0][1];
    int   yb0 = syo[1][0], yb1 = syo[1][1];
    float wa0 = swy[0][0], wa1 = swy[0][1];
    float wb0 = swy[1][0], wb1 = swy[1][1];

    const __half2 hz = __float2half2_rn(0.0f);

#pragma unroll
    for (int ow = 0; ow < 7; ow++) {
        int s0 = 2 * ow;
        int   x00 = sxo[s0][0],     x01 = sxo[s0][1];
        float u00 = swx[s0][0],     u01 = swx[s0][1];
        int   x10 = sxo[s0 + 1][0], x11 = sxo[s0 + 1][1];
        float u10 = swx[s0 + 1][0], u11 = swx[s0 + 1][1];

        __half2 A[4] = {hz, hz, hz, hz};
        __half2 B[4] = {hz, hz, hz, hz};

        // sub-sample 0 (8 taps) -> A
        TAP(x00, u00, ya0, wa0, A)  TAP(x00, u00, ya1, wa1, A)
        TAP(x00, u00, yb0, wb0, A)  TAP(x00, u00, yb1, wb1, A)
        TAP(x01, u01, ya0, wa0, A)  TAP(x01, u01, ya1, wa1, A)
        TAP(x01, u01, yb0, wb0, A)  TAP(x01, u01, yb1, wb1, A)
        // sub-sample 1 (8 taps) -> B
        TAP(x10, u10, ya0, wa0, B)  TAP(x10, u10, ya1, wa1, B)
        TAP(x10, u10, yb0, wb0, B)  TAP(x10, u10, yb1, wb1, B)
        TAP(x11, u11, ya0, wa0, B)  TAP(x11, u11, ya1, wa1, B)
        TAP(x11, u11, yb0, wb0, B)  TAP(x11, u11, yb1, wb1, B)

        __half2 c0 = __hadd2(A[0], B[0]);
        __half2 c1 = __hadd2(A[1], B[1]);
        __half2 c2 = __hadd2(A[2], B[2]);
        __half2 c3 = __hadd2(A[3], B[3]);
        uint4 st;
        st.x = *(unsigned*)&c0;  st.y = *(unsigned*)&c1;
        st.z = *(unsigned*)&c2;  st.w = *(unsigned*)&c3;
        s_out4[ow * 96 + tid] = st;
    }
    __syncthreads();

    // global store: element (c, ow) lives at s_half[ow*768 + c]
    const __half* sh = (const __half*)s_out4;
    float* base = out + ((size_t)roi * C_TOT) * 49 + oh * 7;
#pragma unroll 8
    for (int i = tid; i < C_TOT * 7; i += 96) {
        int c = i / 7, owv = i - 7 * c;
        base[(size_t)c * 49 + owv] = __half2float(sh[owv * C_TOT + c]);
    }
}

// ---------------------------------------------------------------------------
// Launch
// ---------------------------------------------------------------------------
extern "C" void kernel_launch(void* const* d_in, const int* in_sizes, int n_in,
                              void* d_out, int out_size) {
    const float* feat0 = (const float*)d_in[0];
    const float* feat1 = (const float*)d_in[1];
    const float* feat2 = (const float*)d_in[2];
    const float* boxes = (const float*)d_in[3];
    const int*   img_h = (const int*)d_in[4];
    const int*   img_w = (const int*)d_in[5];
    float* out = (float*)d_out;

    int N = in_sizes[3] / 4;

    prep_all<<<PREP_BLOCKS, 256>>>(feat0, feat1, feat2);
    roi_kernel<<<dim3(N, 7), 96>>>(boxes, img_h, img_w, out);
}

// round 10
// speedup vs baseline: 1.0034x; 1.0034x over previous
#include <cuda_runtime.h>
#include <cuda_fp16.h>
#include <cstdint>

#define H0 200
#define W0 304
#define H1 100
#define W1 152
#define H2 50
#define W2 76
#define HW0 (H0*W0)
#define C_TOT 768

// Fused HWC fp16 map, 16B-aligned: [H0*W0][96 octets of 8ch]
__device__ uint4 g_fused[(size_t)HW0 * (C_TOT/8)];

// ---------------------------------------------------------------------------
// Unified prep kernel: one launch, three regions run concurrently.
//  region 0 (8000 blocks): transpose feat0 -> ch [0,256)
//  region 1 (2000 blocks): 2x upsample feat1 -> ch [256,512)
//  region 2 (2000 blocks): 4x upsample feat2 -> ch [512,768) (64px tiles)
// Interleave 20:5:5 per 30 blocks. smem union = 16.6KB -> high occupancy.
// ---------------------------------------------------------------------------
#define P1_PAD 65
#define P2_PAD 65
#define PREP_BLOCKS 12000

__global__ __launch_bounds__(256) void prep_all(
    const float* __restrict__ f0,
    const float* __restrict__ f1,
    const float* __restrict__ f2)
{
    __shared__ char smem_u[2 * 64 * P2_PAD * 2];   // 16640B union
    int warp = threadIdx.x >> 5, lane = threadIdx.x & 31;
    __half* gf = (__half*)g_fused;

    int gq = blockIdx.x / 30, r = blockIdx.x % 30;
    if (r < 20) {
        // ---------------- region 0: transpose feat0 ----------------
        int idx = gq * 20 + r;
        int xi = idx % 10; int t = idx / 10;
        int y = t % 200;   int g = t / 200;
        int xblk = xi * 32;
        int x = xblk + lane;
        int c0 = g * 64;
        float (*tile)[33] = (float(*)[33])smem_u;
        if (x < W0) {
            const float* src = f0 + (size_t)c0 * HW0 + y * W0 + x;
#pragma unroll
            for (int p = 0; p < 8; p++) {
                int cl = warp * 8 + p;
                tile[cl][lane] = __ldg(src + (size_t)cl * HW0);
            }
        }
        __syncthreads();
#pragma unroll
        for (int q = 0; q < 4; q++) {
            int px = warp * 4 + q, xg = xblk + px;
            if (xg < W0) {
                __half2 v = __floats2half2_rn(tile[2 * lane][px], tile[2 * lane + 1][px]);
                *(__half2*)(gf + (size_t)(y * W0 + xg) * C_TOT + c0 + 2 * lane) = v;
            }
        }
    } else if (r < 25) {
        // ---------------- region 1: 2x upsample feat1 ----------------
        int idx = gq * 5 + (r - 20);
        int xi = idx % 5; int t = idx / 5;
        int Y = t % 100;  int cb = (t / 100) * 64;
        int xb = xi * 64;
        __half* tile = (__half*)smem_u;     // [2*64][P1_PAD]
        int j  = xb / 2 + lane;
        int xm = max(j - 1, 0), xc = min(j, W1 - 1), xp = min(j + 1, W1 - 1);
        int r0 = max(Y - 1, 0), r1 = Y, r2 = min(Y + 1, H1 - 1);
#pragma unroll
        for (int p = 0; p < 8; p++) {
            int cl = warp * 8 + p;
            const float* pl = f1 + (size_t)(cb + cl) * (H1 * W1);
            float v00 = __ldg(pl + r0 * W1 + xm), v01 = __ldg(pl + r0 * W1 + xc), v02 = __ldg(pl + r0 * W1 + xp);
            float v10 = __ldg(pl + r1 * W1 + xm), v11 = __ldg(pl + r1 * W1 + xc), v12 = __ldg(pl + r1 * W1 + xp);
            float v20 = __ldg(pl + r2 * W1 + xm), v21 = __ldg(pl + r2 * W1 + xc), v22 = __ldg(pl + r2 * W1 + xp);
            float a0 = 0.25f * v00 + 0.75f * v01, b0 = 0.75f * v01 + 0.25f * v02;
            float a1 = 0.25f * v10 + 0.75f * v11, b1 = 0.75f * v11 + 0.25f * v12;
            float a2 = 0.25f * v20 + 0.75f * v21, b2 = 0.75f * v21 + 0.25f * v22;
            float e0 = 0.25f * a0 + 0.75f * a1, o0 = 0.25f * b0 + 0.75f * b1;
            float e1 = 0.75f * a1 + 0.25f * a2, o1 = 0.75f * b1 + 0.25f * b2;
            int px = 2 * lane;
            tile[(0 * 64 + px)     * P1_PAD + cl] = __float2half_rn(e0);
            tile[(0 * 64 + px + 1) * P1_PAD + cl] = __float2half_rn(o0);
            tile[(1 * 64 + px)     * P1_PAD + cl] = __float2half_rn(e1);
            tile[(1 * 64 + px + 1) * P1_PAD + cl] = __float2half_rn(o1);
        }
        __syncthreads();
        for (int i = warp; i < 128; i += 8) {
            int row = i >> 6, px = i & 63;
            int xg = xb + px;
            if (xg < W0) {
                __half lo = tile[(row * 64 + px) * P1_PAD + 2 * lane];
                __half hi = tile[(row * 64 + px) * P1_PAD + 2 * lane + 1];
                *(__half2*)(gf + (size_t)((2 * Y + row) * W0 + xg) * C_TOT + 256 + cb + 2 * lane)
                    = __halves2half2(lo, hi);
            }
        }
    } else {
        // ---------------- region 2: 4x upsample feat2 (64px tiles) --------
        int idx = gq * 5 + (r - 25);
        int xi = idx % 5; int t = idx / 5;
        int yb = t % 100; int cb = (t / 100) * 64;
        int xb = xi * 64;
        __half* tile = (__half*)smem_u;     // [2*64][P2_PAD]
        int Y = yb >> 1, half = yb & 1;
        int ra = half ? Y : max(Y - 1, 0);
        int rb = half ? min(Y + 1, H2 - 1) : Y;
        float wya0, wyb0, wya1, wyb1;
        if (half == 0) { wya0 = 0.375f; wyb0 = 0.625f; wya1 = 0.125f; wyb1 = 0.875f; }
        else           { wya0 = 0.875f; wyb0 = 0.125f; wya1 = 0.625f; wyb1 = 0.375f; }
        if (lane < 16) {
            int j  = xb / 4 + lane;
            int xm = max(j - 1, 0), xc = min(j, W2 - 1), xp = min(j + 1, W2 - 1);
#pragma unroll
            for (int p = 0; p < 8; p++) {
                int cl = warp * 8 + p;
                const float* pl = f2 + (size_t)(cb + cl) * (H2 * W2);
                float va0 = __ldg(pl + ra * W2 + xm), va1 = __ldg(pl + ra * W2 + xc), va2 = __ldg(pl + ra * W2 + xp);
                float vb0 = __ldg(pl + rb * W2 + xm), vb1 = __ldg(pl + rb * W2 + xc), vb2 = __ldg(pl + rb * W2 + xp);
                float qa[4], qb[4];
                qa[0] = 0.375f * va0 + 0.625f * va1; qa[1] = 0.125f * va0 + 0.875f * va1;
                qa[2] = 0.875f * va1 + 0.125f * va2; qa[3] = 0.625f * va1 + 0.375f * va2;
                qb[0] = 0.375f * vb0 + 0.625f * vb1; qb[1] = 0.125f * vb0 + 0.875f * vb1;
                qb[2] = 0.875f * vb1 + 0.125f * vb2; qb[3] = 0.625f * vb1 + 0.375f * vb2;
                int px = 4 * lane;
#pragma unroll
                for (int q = 0; q < 4; q++) {
                    float o0 = wya0 * qa[q] + wyb0 * qb[q];
                    float o1 = wya1 * qa[q] + wyb1 * qb[q];
                    tile[(0 * 64 + px + q) * P2_PAD + cl] = __float2half_rn(o0);
                    tile[(1 * 64 + px + q) * P2_PAD + cl] = __float2half_rn(o1);
                }
            }
        }
        __syncthreads();
        int ybase = 4 * Y + 2 * half;
        for (int i = warp; i < 128; i += 8) {
            int row = i >> 6, px = i & 63;
            int xg = xb + px;
            if (xg < W0) {
                __half lo = tile[(row * 64 + px) * P2_PAD + 2 * lane];
                __half hi = tile[(row * 64 + px) * P2_PAD + 2 * lane + 1];
                *(__half2*)(gf + (size_t)((ybase + row) * W0 + xg) * C_TOT + 512 + cb + 2 * lane)
                    = __halves2half2(lo, hi);
            }
        }
    }
}

// ---------------------------------------------------------------------------
// RoIAlign: grid (N, 7 oh), block 672 = 7 ow x 96 octets.
// Thread = one (ow, 8-channel octet): 16 HFMA2 taps, two 8-tap trees.
// Low register pressure -> 2 blocks/SM (~65% occ) for latency hiding.
// ---------------------------------------------------------------------------
#define OPP 96   // uint4 octets per pixel

#define TAP(xo, ux, yo, wy, A) { \
    uint4 v = __ldg(fp + (yo) + (xo)); \
    __half2 kh = __float2half2_rn((wy) * (ux)); \
    A[0] = __hfma2(kh, *(__half2*)&v.x, A[0]); \
    A[1] = __hfma2(kh, *(__half2*)&v.y, A[1]); \
    A[2] = __hfma2(kh, *(__half2*)&v.z, A[2]); \
    A[3] = __hfma2(kh, *(__half2*)&v.w, A[3]); }

__global__ __launch_bounds__(672, 2) void roi_kernel(
    const float* __restrict__ boxes,
    const int*   __restrict__ img_h,
    const int*   __restrict__ img_w,
    float* __restrict__ out)
{
    int roi = blockIdx.x;
    int oh  = blockIdx.y;
    int tid = threadIdx.x;          // 0..671
    int ow    = tid / 96;
    int octet = tid - ow * 96;

    __shared__ int   sxo[14][2];    // x corner offsets (uint4 units)
    __shared__ float swx[14][2];
    __shared__ int   syo[2][2];     // y corner offsets (uint4 units)
    __shared__ float swy[2][2];     // scaled by 0.25
    __shared__ uint4 s_out4[7 * 96];

    if (tid < 16) {
        bool isx = tid < 14;
        int  s, bin;
        if (isx) { s = tid;      bin = s >> 1; }
        else     { s = tid - 14; bin = oh;     }
        float offs = 0.25f + 0.5f * (float)(isx ? (s & 1) : s);

        float scale = isx ? ((float)W0 / (float)__ldg(img_w))
                          : ((float)H0 / (float)__ldg(img_h));
        float p1 = __ldg(boxes + roi * 4 + (isx ? 0 : 1)) * scale;
        float p2 = __ldg(boxes + roi * 4 + (isx ? 2 : 3)) * scale;
        float bs = fmaxf(p2 - p1, 1.0f) * (1.0f / 7.0f);
        float P  = p1 + ((float)bin + offs) * bs;

        int lim = isx ? W0 : H0;
        bool valid = (P >= -1.0f) && (P <= (float)lim);
        float Pc = fminf(fmaxf(P, 0.0f), (float)(lim - 1));
        int p0  = (int)Pc;
        int p1i = min(p0 + 1, lim - 1);
        float l  = Pc - (float)p0;
        float w0 = valid ? (1.0f - l) : 0.0f;
        float w1 = valid ? l : 0.0f;

        if (isx) {
            sxo[s][0] = p0 * OPP;    sxo[s][1] = p1i * OPP;
            swx[s][0] = w0;          swx[s][1] = w1;
        } else {
            syo[s][0] = p0 * (W0 * OPP);   syo[s][1] = p1i * (W0 * OPP);
            swy[s][0] = w0 * 0.25f;        swy[s][1] = w1 * 0.25f;
        }
    }
    __syncthreads();

    const uint4* fp = g_fused + octet;

    int   ya0 = syo[0][0], ya1 = syo[0][1];
    int   yb0 = syo[1][0], yb1 = syo[1][1];
    float wa0 = swy[0][0], wa1 = swy[0][1];
    float wb0 = swy[1][0], wb1 = swy[1][1];

    int s0 = 2 * ow;
    int   x00 = sxo[s0][0],     x01 = sxo[s0][1];
    float u00 = swx[s0][0],     u01 = swx[s0][1];
    int   x10 = sxo[s0 + 1][0], x11 = sxo[s0 + 1][1];
    float u10 = swx[s0 + 1][0], u11 = swx[s0 + 1][1];

    const __half2 hz = __float2half2_rn(0.0f);
    __half2 A[4] = {hz, hz, hz, hz};
    __half2 B[4] = {hz, hz, hz, hz};

    // sub-sample 0 (8 taps) -> A
    TAP(x00, u00, ya0, wa0, A)  TAP(x00, u00, ya1, wa1, A)
    TAP(x00, u00, yb0, wb0, A)  TAP(x00, u00, yb1, wb1, A)
    TAP(x01, u01, ya0, wa0, A)  TAP(x01, u01, ya1, wa1, A)
    TAP(x01, u01, yb0, wb0, A)  TAP(x01, u01, yb1, wb1, A)
    // sub-sample 1 (8 taps) -> B
    TAP(x10, u10, ya0, wa0, B)  TAP(x10, u10, ya1, wa1, B)
    TAP(x10, u10, yb0, wb0, B)  TAP(x10, u10, yb1, wb1, B)
    TAP(x11, u11, ya0, wa0, B)  TAP(x11, u11, ya1, wa1, B)
    TAP(x11, u11, yb0, wb0, B)  TAP(x11, u11, yb1, wb1, B)

    __half2 c0 = __hadd2(A[0], B[0]);
    __half2 c1 = __hadd2(A[1], B[1]);
    __half2 c2 = __hadd2(A[2], B[2]);
    __half2 c3 = __hadd2(A[3], B[3]);
    uint4 st;
    st.x = *(unsigned*)&c0;  st.y = *(unsigned*)&c1;
    st.z = *(unsigned*)&c2;  st.w = *(unsigned*)&c3;
    s_out4[ow * 96 + octet] = st;

    __syncthreads();

    // global store: element (c, ow) lives at s_half[ow*768 + c]
    const __half* sh = (const __half*)s_out4;
    float* base = out + ((size_t)roi * C_TOT) * 49 + oh * 7;
#pragma unroll
    for (int i = tid; i < C_TOT * 7; i += 672) {
        int c = i / 7, owv = i - 7 * c;
        base[(size_t)c * 49 + owv] = __half2float(sh[owv * C_TOT + c]);
    }
}

// ---------------------------------------------------------------------------
// Launch
// ---------------------------------------------------------------------------
extern "C" void kernel_launch(void* const* d_in, const int* in_sizes, int n_in,
                              void* d_out, int out_size) {
    const float* feat0 = (const float*)d_in[0];
    const float* feat1 = (const float*)d_in[1];
    const float* feat2 = (const float*)d_in[2];
    const float* boxes = (const float*)d_in[3];
    const int*   img_h = (const int*)d_in[4];
    const int*   img_w = (const int*)d_in[5];
    float* out = (float*)d_out;

    int N = in_sizes[3] / 4;

    prep_all<<<PREP_BLOCKS, 256>>>(feat0, feat1, feat2);
    roi_kernel<<<dim3(N, 7), 672>>>(boxes, img_h, img_w, out);
}

// round 12
// speedup vs baseline: 1.1290x; 1.1253x over previous
#include <cuda_runtime.h>
#include <cuda_fp16.h>
#include <cstdint>

#define H0 200
#define W0 304
#define H1 100
#define W1 152
#define H2 50
#define W2 76
#define HW0 (H0*W0)
#define C_TOT 768

// Fused HWC fp16 map, 16B-aligned: [H0*W0][96 octets of 8ch]
__device__ uint4 g_fused[(size_t)HW0 * (C_TOT/8)];

#define P1_PAD 65
#define P2_PAD 65

// ---------------------------------------------------------------------------
// prep0: transpose feat0 (CHW fp32) -> g_fused channels [0,256)
// ---------------------------------------------------------------------------
__global__ __launch_bounds__(256) void prep0_kernel(const float* __restrict__ f0) {
    __shared__ float tile[64][33];
    int y = blockIdx.y, xblk = blockIdx.x * 32, g = blockIdx.z;
    int warp = threadIdx.x >> 5, lane = threadIdx.x & 31;
    int x = xblk + lane;
    int c0 = g * 64;
    __half* gf = (__half*)g_fused;
    if (x < W0) {
        const float* src = f0 + (size_t)c0 * HW0 + y * W0 + x;
#pragma unroll
        for (int p = 0; p < 8; p++) {
            int cl = warp * 8 + p;
            tile[cl][lane] = __ldg(src + (size_t)cl * HW0);
        }
    }
    __syncthreads();
#pragma unroll
    for (int q = 0; q < 4; q++) {
        int px = warp * 4 + q, xg = xblk + px;
        if (xg < W0) {
            __half2 v = __floats2half2_rn(tile[2 * lane][px], tile[2 * lane + 1][px]);
            *(__half2*)(gf + (size_t)(y * W0 + xg) * C_TOT + c0 + 2 * lane) = v;
        }
    }
}

// ---------------------------------------------------------------------------
// prep1: 2x upsample feat1 -> channels [256,512). Constant-phase separable.
// ---------------------------------------------------------------------------
__global__ __launch_bounds__(256) void prep1_kernel(const float* __restrict__ f1) {
    __shared__ __half tile[2 * 64 * P1_PAD];
    int Y  = blockIdx.y;
    int xb = blockIdx.x * 64;
    int cb = blockIdx.z * 64;
    int warp = threadIdx.x >> 5, lane = threadIdx.x & 31;
    __half* gf = (__half*)g_fused;
    int j  = xb / 2 + lane;
    int xm = max(j - 1, 0), xc = min(j, W1 - 1), xp = min(j + 1, W1 - 1);
    int r0 = max(Y - 1, 0), r1 = Y, r2 = min(Y + 1, H1 - 1);
#pragma unroll
    for (int p = 0; p < 8; p++) {
        int cl = warp * 8 + p;
        const float* pl = f1 + (size_t)(cb + cl) * (H1 * W1);
        float v00 = __ldg(pl + r0 * W1 + xm), v01 = __ldg(pl + r0 * W1 + xc), v02 = __ldg(pl + r0 * W1 + xp);
        float v10 = __ldg(pl + r1 * W1 + xm), v11 = __ldg(pl + r1 * W1 + xc), v12 = __ldg(pl + r1 * W1 + xp);
        float v20 = __ldg(pl + r2 * W1 + xm), v21 = __ldg(pl + r2 * W1 + xc), v22 = __ldg(pl + r2 * W1 + xp);
        float a0 = 0.25f * v00 + 0.75f * v01, b0 = 0.75f * v01 + 0.25f * v02;
        float a1 = 0.25f * v10 + 0.75f * v11, b1 = 0.75f * v11 + 0.25f * v12;
        float a2 = 0.25f * v20 + 0.75f * v21, b2 = 0.75f * v21 + 0.25f * v22;
        float e0 = 0.25f * a0 + 0.75f * a1, o0 = 0.25f * b0 + 0.75f * b1;
        float e1 = 0.75f * a1 + 0.25f * a2, o1 = 0.75f * b1 + 0.25f * b2;
        int px = 2 * lane;
        tile[(0 * 64 + px)     * P1_PAD + cl] = __float2half_rn(e0);
        tile[(0 * 64 + px + 1) * P1_PAD + cl] = __float2half_rn(o0);
        tile[(1 * 64 + px)     * P1_PAD + cl] = __float2half_rn(e1);
        tile[(1 * 64 + px + 1) * P1_PAD + cl] = __float2half_rn(o1);
    }
    __syncthreads();
    for (int i = warp; i < 128; i += 8) {
        int row = i >> 6, px = i & 63;
        int xg = xb + px;
        if (xg < W0) {
            __half lo = tile[(row * 64 + px) * P1_PAD + 2 * lane];
            __half hi = tile[(row * 64 + px) * P1_PAD + 2 * lane + 1];
            *(__half2*)(gf + (size_t)((2 * Y + row) * W0 + xg) * C_TOT + 256 + cb + 2 * lane)
                = __halves2half2(lo, hi);
        }
    }
}

// ---------------------------------------------------------------------------
// prep2: 4x upsample feat2 -> channels [512,768). 64px tiles.
// ---------------------------------------------------------------------------
__global__ __launch_bounds__(256) void prep2_kernel(const float* __restrict__ f2) {
    __shared__ __half tile[2 * 64 * P2_PAD];
    int yb = blockIdx.y;
    int xb = blockIdx.x * 64;
    int cb = blockIdx.z * 64;
    int warp = threadIdx.x >> 5, lane = threadIdx.x & 31;
    __half* gf = (__half*)g_fused;
    int Y = yb >> 1, half = yb & 1;
    int ra = half ? Y : max(Y - 1, 0);
    int rb = half ? min(Y + 1, H2 - 1) : Y;
    float wya0, wyb0, wya1, wyb1;
    if (half == 0) { wya0 = 0.375f; wyb0 = 0.625f; wya1 = 0.125f; wyb1 = 0.875f; }
    else           { wya0 = 0.875f; wyb0 = 0.125f; wya1 = 0.625f; wyb1 = 0.375f; }
    if (lane < 16) {
        int j  = xb / 4 + lane;
        int xm = max(j - 1, 0), xc = min(j, W2 - 1), xp = min(j + 1, W2 - 1);
#pragma unroll
        for (int p = 0; p < 8; p++) {
            int cl = warp * 8 + p;
            const float* pl = f2 + (size_t)(cb + cl) * (H2 * W2);
            float va0 = __ldg(pl + ra * W2 + xm), va1 = __ldg(pl + ra * W2 + xc), va2 = __ldg(pl + ra * W2 + xp);
            float vb0 = __ldg(pl + rb * W2 + xm), vb1 = __ldg(pl + rb * W2 + xc), vb2 = __ldg(pl + rb * W2 + xp);
            float qa[4], qb[4];
            qa[0] = 0.375f * va0 + 0.625f * va1; qa[1] = 0.125f * va0 + 0.875f * va1;
            qa[2] = 0.875f * va1 + 0.125f * va2; qa[3] = 0.625f * va1 + 0.375f * va2;
            qb[0] = 0.375f * vb0 + 0.625f * vb1; qb[1] = 0.125f * vb0 + 0.875f * vb1;
            qb[2] = 0.875f * vb1 + 0.125f * vb2; qb[3] = 0.625f * vb1 + 0.375f * vb2;
            int px = 4 * lane;
#pragma unroll
            for (int q = 0; q < 4; q++) {
                float o0 = wya0 * qa[q] + wyb0 * qb[q];
                float o1 = wya1 * qa[q] + wyb1 * qb[q];
                tile[(0 * 64 + px + q) * P2_PAD + cl] = __float2half_rn(o0);
                tile[(1 * 64 + px + q) * P2_PAD + cl] = __float2half_rn(o1);
            }
        }
    }
    __syncthreads();
    int ybase = 4 * Y + 2 * half;
    for (int i = warp; i < 128; i += 8) {
        int row = i >> 6, px = i & 63;
        int xg = xb + px;
        if (xg < W0) {
            __half lo = tile[(row * 64 + px) * P2_PAD + 2 * lane];
            __half hi = tile[(row * 64 + px) * P2_PAD + 2 * lane + 1];
            *(__half2*)(gf + (size_t)((ybase + row) * W0 + xg) * C_TOT + 512 + cb + 2 * lane)
                = __halves2half2(lo, hi);
        }
    }
}

// ---------------------------------------------------------------------------
// RoIAlign over one 256-channel slab: grid (N,7 oh), block 224 = 7 ow x 32 oct.
// Thread = one (ow, octet): 16 HFMA2 taps, two 8-tap trees.
// ---------------------------------------------------------------------------
#define OPP 96   // uint4 octets per pixel (full row)

#define TAP(xo, ux, yo, wy, A) { \
    uint4 v = __ldg(fp + (yo) + (xo)); \
    __half2 kh = __float2half2_rn((wy) * (ux)); \
    A[0] = __hfma2(kh, *(__half2*)&v.x, A[0]); \
    A[1] = __hfma2(kh, *(__half2*)&v.y, A[1]); \
    A[2] = __hfma2(kh, *(__half2*)&v.z, A[2]); \
    A[3] = __hfma2(kh, *(__half2*)&v.w, A[3]); }

__global__ __launch_bounds__(224) void roi_slab_kernel(
    const float* __restrict__ boxes,
    const int*   __restrict__ img_h,
    const int*   __restrict__ img_w,
    float* __restrict__ out,
    int slab)
{
    int roi = blockIdx.x;
    int oh  = blockIdx.y;
    int tid = threadIdx.x;          // 0..223
    int ow    = tid >> 5;
    int octet = tid & 31;

    __shared__ int   sxo[14][2];
    __shared__ float swx[14][2];
    __shared__ int   syo[2][2];
    __shared__ float swy[2][2];     // scaled by 0.25
    __shared__ uint4 s_out4[7 * 32];

    if (tid < 16) {
        bool isx = tid < 14;
        int  s, bin;
        if (isx) { s = tid;      bin = s >> 1; }
        else     { s = tid - 14; bin = oh;     }
        float offs = 0.25f + 0.5f * (float)(isx ? (s & 1) : s);

        float scale = isx ? ((float)W0 / (float)__ldg(img_w))
                          : ((float)H0 / (float)__ldg(img_h));
        float p1 = __ldg(boxes + roi * 4 + (isx ? 0 : 1)) * scale;
        float p2 = __ldg(boxes + roi * 4 + (isx ? 2 : 3)) * scale;
        float bs = fmaxf(p2 - p1, 1.0f) * (1.0f / 7.0f);
        float P  = p1 + ((float)bin + offs) * bs;

        int lim = isx ? W0 : H0;
        bool valid = (P >= -1.0f) && (P <= (float)lim);
        float Pc = fminf(fmaxf(P, 0.0f), (float)(lim - 1));
        int p0  = (int)Pc;
        int p1i = min(p0 + 1, lim - 1);
        float l  = Pc - (float)p0;
        float w0 = valid ? (1.0f - l) : 0.0f;
        float w1 = valid ? l : 0.0f;

        if (isx) {
            sxo[s][0] = p0 * OPP;    sxo[s][1] = p1i * OPP;
            swx[s][0] = w0;          swx[s][1] = w1;
        } else {
            syo[s][0] = p0 * (W0 * OPP);   syo[s][1] = p1i * (W0 * OPP);
            swy[s][0] = w0 * 0.25f;        swy[s][1] = w1 * 0.25f;
        }
    }
    __syncthreads();

    const uint4* fp = g_fused + slab * 32 + octet;

    int   ya0 = syo[0][0], ya1 = syo[0][1];
    int   yb0 = syo[1][0], yb1 = syo[1][1];
    float wa0 = swy[0][0], wa1 = swy[0][1];
    float wb0 = swy[1][0], wb1 = swy[1][1];

    int s0 = 2 * ow;
    int   x00 = sxo[s0][0],     x01 = sxo[s0][1];
    float u00 = swx[s0][0],     u01 = swx[s0][1];
    int   x10 = sxo[s0 + 1][0], x11 = sxo[s0 + 1][1];
    float u10 = swx[s0 + 1][0], u11 = swx[s0 + 1][1];

    const __half2 hz = __float2half2_rn(0.0f);
    __half2 A[4] = {hz, hz, hz, hz};
    __half2 B[4] = {hz, hz, hz, hz};

    TAP(x00, u00, ya0, wa0, A)  TAP(x00, u00, ya1, wa1, A)
    TAP(x00, u00, yb0, wb0, A)  TAP(x00, u00, yb1, wb1, A)
    TAP(x01, u01, ya0, wa0, A)  TAP(x01, u01, ya1, wa1, A)
    TAP(x01, u01, yb0, wb0, A)  TAP(x01, u01, yb1, wb1, A)
    TAP(x10, u10, ya0, wa0, B)  TAP(x10, u10, ya1, wa1, B)
    TAP(x10, u10, yb0, wb0, B)  TAP(x10, u10, yb1, wb1, B)
    TAP(x11, u11, ya0, wa0, B)  TAP(x11, u11, ya1, wa1, B)
    TAP(x11, u11, yb0, wb0, B)  TAP(x11, u11, yb1, wb1, B)

    __half2 c0 = __hadd2(A[0], B[0]);
    __half2 c1 = __hadd2(A[1], B[1]);
    __half2 c2 = __hadd2(A[2], B[2]);
    __half2 c3 = __hadd2(A[3], B[3]);
    uint4 st;
    st.x = *(unsigned*)&c0;  st.y = *(unsigned*)&c1;
    st.z = *(unsigned*)&c2;  st.w = *(unsigned*)&c3;
    s_out4[ow * 32 + octet] = st;

    __syncthreads();

    // element (c_local, ow) lives at sh[ow*256 + c_local]
    const __half* sh = (const __half*)s_out4;
    float* base = out + ((size_t)roi * C_TOT + slab * 256) * 49 + oh * 7;
#pragma unroll
    for (int i = tid; i < 256 * 7; i += 224) {
        int c = i / 7, owv = i - 7 * c;
        base[(size_t)c * 49 + owv] = __half2float(sh[owv * 256 + c]);
    }
}

// ---------------------------------------------------------------------------
// Launch: 3 independent prep->roi chains on 3 streams (fork-join capture).
// ---------------------------------------------------------------------------
namespace {
struct Aux {
    cudaStream_t s1, s2;
    cudaEvent_t fork, j1, j2;
    Aux() {
        cudaStreamCreateWithFlags(&s1, cudaStreamNonBlocking);
        cudaStreamCreateWithFlags(&s2, cudaStreamNonBlocking);
        cudaEventCreateWithFlags(&fork, cudaEventDisableTiming);
        cudaEventCreateWithFlags(&j1, cudaEventDisableTiming);
        cudaEventCreateWithFlags(&j2, cudaEventDisableTiming);
    }
};
Aux& aux() { static Aux a; return a; }
}

extern "C" void kernel_launch(void* const* d_in, const int* in_sizes, int n_in,
                              void* d_out, int out_size) {
    const float* feat0 = (const float*)d_in[0];
    const float* feat1 = (const float*)d_in[1];
    const float* feat2 = (const float*)d_in[2];
    const float* boxes = (const float*)d_in[3];
    const int*   img_h = (const int*)d_in[4];
    const int*   img_w = (const int*)d_in[5];
    float* out = (float*)d_out;

    int N = in_sizes[3] / 4;
    Aux& a = aux();

    // fork from default (capture-origin) stream
    cudaEventRecord(a.fork, 0);
    cudaStreamWaitEvent(a.s1, a.fork, 0);
    cudaStreamWaitEvent(a.s2, a.fork, 0);

    // chain 0 on default stream
    prep0_kernel<<<dim3(10, 200, 4), 256>>>(feat0);
    roi_slab_kernel<<<dim3(N, 7), 224>>>(boxes, img_h, img_w, out, 0);

    // chain 1 on s1
    prep1_kernel<<<dim3(5, 100, 4), 256, 0, a.s1>>>(feat1);
    roi_slab_kernel<<<dim3(N, 7), 224, 0, a.s1>>>(boxes, img_h, img_w, out, 1);

    // chain 2 on s2
    prep2_kernel<<<dim3(5, 100, 4), 256, 0, a.s2>>>(feat2);
    roi_slab_kernel<<<dim3(N, 7), 224, 0, a.s2>>>(boxes, img_h, img_w, out, 2);

    // join back to default stream
    cudaEventRecord(a.j1, a.s1);
    cudaEventRecord(a.j2, a.s2);
    cudaStreamWaitEvent(0, a.j1, 0);
    cudaStreamWaitEvent(0, a.j2, 0);
}

// round 13
// speedup vs baseline: 1.1459x; 1.0150x over previous
#include <cuda_runtime.h>
#include <cuda_fp16.h>
#include <cstdint>

#define H0 200
#define W0 304
#define H1 100
#define W1 152
#define H2 50
#define W2 76
#define HW0 (H0*W0)
#define C_TOT 768

// Fused HWC fp16 map, 16B-aligned: [H0*W0][96 octets of 8ch]
__device__ uint4 g_fused[(size_t)HW0 * (C_TOT/8)];

#define P1_PAD 65
#define P2_PAD 65

// ---------------------------------------------------------------------------
// prep0: transpose feat0 (CHW fp32) -> g_fused channels [0,256)
// ---------------------------------------------------------------------------
__global__ __launch_bounds__(256) void prep0_kernel(const float* __restrict__ f0) {
    __shared__ float tile[64][33];
    int y = blockIdx.y, xblk = blockIdx.x * 32, g = blockIdx.z;
    int warp = threadIdx.x >> 5, lane = threadIdx.x & 31;
    int x = xblk + lane;
    int c0 = g * 64;
    __half* gf = (__half*)g_fused;
    if (x < W0) {
        const float* src = f0 + (size_t)c0 * HW0 + y * W0 + x;
#pragma unroll
        for (int p = 0; p < 8; p++) {
            int cl = warp * 8 + p;
            tile[cl][lane] = __ldg(src + (size_t)cl * HW0);
        }
    }
    __syncthreads();
#pragma unroll
    for (int q = 0; q < 4; q++) {
        int px = warp * 4 + q, xg = xblk + px;
        if (xg < W0) {
            __half2 v = __floats2half2_rn(tile[2 * lane][px], tile[2 * lane + 1][px]);
            *(__half2*)(gf + (size_t)(y * W0 + xg) * C_TOT + c0 + 2 * lane) = v;
        }
    }
}

// ---------------------------------------------------------------------------
// prep1: 2x upsample feat1 -> channels [256,512). Constant-phase separable.
// ---------------------------------------------------------------------------
__global__ __launch_bounds__(256) void prep1_kernel(const float* __restrict__ f1) {
    __shared__ __half tile[2 * 64 * P1_PAD];
    int Y  = blockIdx.y;
    int xb = blockIdx.x * 64;
    int cb = blockIdx.z * 64;
    int warp = threadIdx.x >> 5, lane = threadIdx.x & 31;
    __half* gf = (__half*)g_fused;
    int j  = xb / 2 + lane;
    int xm = max(j - 1, 0), xc = min(j, W1 - 1), xp = min(j + 1, W1 - 1);
    int r0 = max(Y - 1, 0), r1 = Y, r2 = min(Y + 1, H1 - 1);
#pragma unroll
    for (int p = 0; p < 8; p++) {
        int cl = warp * 8 + p;
        const float* pl = f1 + (size_t)(cb + cl) * (H1 * W1);
        float v00 = __ldg(pl + r0 * W1 + xm), v01 = __ldg(pl + r0 * W1 + xc), v02 = __ldg(pl + r0 * W1 + xp);
        float v10 = __ldg(pl + r1 * W1 + xm), v11 = __ldg(pl + r1 * W1 + xc), v12 = __ldg(pl + r1 * W1 + xp);
        float v20 = __ldg(pl + r2 * W1 + xm), v21 = __ldg(pl + r2 * W1 + xc), v22 = __ldg(pl + r2 * W1 + xp);
        float a0 = 0.25f * v00 + 0.75f * v01, b0 = 0.75f * v01 + 0.25f * v02;
        float a1 = 0.25f * v10 + 0.75f * v11, b1 = 0.75f * v11 + 0.25f * v12;
        float a2 = 0.25f * v20 + 0.75f * v21, b2 = 0.75f * v21 + 0.25f * v22;
        float e0 = 0.25f * a0 + 0.75f * a1, o0 = 0.25f * b0 + 0.75f * b1;
        float e1 = 0.75f * a1 + 0.25f * a2, o1 = 0.75f * b1 + 0.25f * b2;
        int px = 2 * lane;
        tile[(0 * 64 + px)     * P1_PAD + cl] = __float2half_rn(e0);
        tile[(0 * 64 + px + 1) * P1_PAD + cl] = __float2half_rn(o0);
        tile[(1 * 64 + px)     * P1_PAD + cl] = __float2half_rn(e1);
        tile[(1 * 64 + px + 1) * P1_PAD + cl] = __float2half_rn(o1);
    }
    __syncthreads();
    for (int i = warp; i < 128; i += 8) {
        int row = i >> 6, px = i & 63;
        int xg = xb + px;
        if (xg < W0) {
            __half lo = tile[(row * 64 + px) * P1_PAD + 2 * lane];
            __half hi = tile[(row * 64 + px) * P1_PAD + 2 * lane + 1];
            *(__half2*)(gf + (size_t)((2 * Y + row) * W0 + xg) * C_TOT + 256 + cb + 2 * lane)
                = __halves2half2(lo, hi);
        }
    }
}

// ---------------------------------------------------------------------------
// prep2: 4x upsample feat2 -> channels [512,768). 64px tiles.
// ---------------------------------------------------------------------------
__global__ __launch_bounds__(256) void prep2_kernel(const float* __restrict__ f2) {
    __shared__ __half tile[2 * 64 * P2_PAD];
    int yb = blockIdx.y;
    int xb = blockIdx.x * 64;
    int cb = blockIdx.z * 64;
    int warp = threadIdx.x >> 5, lane = threadIdx.x & 31;
    __half* gf = (__half*)g_fused;
    int Y = yb >> 1, half = yb & 1;
    int ra = half ? Y : max(Y - 1, 0);
    int rb = half ? min(Y + 1, H2 - 1) : Y;
    float wya0, wyb0, wya1, wyb1;
    if (half == 0) { wya0 = 0.375f; wyb0 = 0.625f; wya1 = 0.125f; wyb1 = 0.875f; }
    else           { wya0 = 0.875f; wyb0 = 0.125f; wya1 = 0.625f; wyb1 = 0.375f; }
    if (lane < 16) {
        int j  = xb / 4 + lane;
        int xm = max(j - 1, 0), xc = min(j, W2 - 1), xp = min(j + 1, W2 - 1);
#pragma unroll
        for (int p = 0; p < 8; p++) {
            int cl = warp * 8 + p;
            const float* pl = f2 + (size_t)(cb + cl) * (H2 * W2);
            float va0 = __ldg(pl + ra * W2 + xm), va1 = __ldg(pl + ra * W2 + xc), va2 = __ldg(pl + ra * W2 + xp);
            float vb0 = __ldg(pl + rb * W2 + xm), vb1 = __ldg(pl + rb * W2 + xc), vb2 = __ldg(pl + rb * W2 + xp);
            float qa[4], qb[4];
            qa[0] = 0.375f * va0 + 0.625f * va1; qa[1] = 0.125f * va0 + 0.875f * va1;
            qa[2] = 0.875f * va1 + 0.125f * va2; qa[3] = 0.625f * va1 + 0.375f * va2;
            qb[0] = 0.375f * vb0 + 0.625f * vb1; qb[1] = 0.125f * vb0 + 0.875f * vb1;
            qb[2] = 0.875f * vb1 + 0.125f * vb2; qb[3] = 0.625f * vb1 + 0.375f * vb2;
            int px = 4 * lane;
#pragma unroll
            for (int q = 0; q < 4; q++) {
                float o0 = wya0 * qa[q] + wyb0 * qb[q];
                float o1 = wya1 * qa[q] + wyb1 * qb[q];
                tile[(0 * 64 + px + q) * P2_PAD + cl] = __float2half_rn(o0);
                tile[(1 * 64 + px + q) * P2_PAD + cl] = __float2half_rn(o1);
            }
        }
    }
    __syncthreads();
    int ybase = 4 * Y + 2 * half;
    for (int i = warp; i < 128; i += 8) {
        int row = i >> 6, px = i & 63;
        int xg = xb + px;
        if (xg < W0) {
            __half lo = tile[(row * 64 + px) * P2_PAD + 2 * lane];
            __half hi = tile[(row * 64 + px) * P2_PAD + 2 * lane + 1];
            *(__half2*)(gf + (size_t)((ybase + row) * W0 + xg) * C_TOT + 512 + cb + 2 * lane)
                = __halves2half2(lo, hi);
        }
    }
}

// ---------------------------------------------------------------------------
// RoIAlign over one 256-channel slab: grid (N,7 oh), block 224 = 7 ow x 32 oct.
// Thread = one (ow, octet): 16 taps in TWO bursts of 8 batched LDG.128s
// (explicit temporaries -> MLP=8), then HFMA2 trees.
// ---------------------------------------------------------------------------
#define OPP 96   // uint4 octets per pixel (full row)

#define FMA8(t, kh, A) { \
    A[0] = __hfma2(kh, *(__half2*)&t.x, A[0]); \
    A[1] = __hfma2(kh, *(__half2*)&t.y, A[1]); \
    A[2] = __hfma2(kh, *(__half2*)&t.z, A[2]); \
    A[3] = __hfma2(kh, *(__half2*)&t.w, A[3]); }

__global__ __launch_bounds__(224) void roi_slab_kernel(
    const float* __restrict__ boxes,
    const int*   __restrict__ img_h,
    const int*   __restrict__ img_w,
    float* __restrict__ out,
    int slab)
{
    int roi = blockIdx.x;
    int oh  = blockIdx.y;
    int tid = threadIdx.x;          // 0..223
    int ow    = tid >> 5;
    int octet = tid & 31;

    __shared__ int   sxo[14][2];
    __shared__ float swx[14][2];
    __shared__ int   syo[2][2];
    __shared__ float swy[2][2];     // scaled by 0.25
    __shared__ uint4 s_out4[7 * 32];

    if (tid < 16) {
        bool isx = tid < 14;
        int  s, bin;
        if (isx) { s = tid;      bin = s >> 1; }
        else     { s = tid - 14; bin = oh;     }
        float offs = 0.25f + 0.5f * (float)(isx ? (s & 1) : s);

        float scale = isx ? ((float)W0 / (float)__ldg(img_w))
                          : ((float)H0 / (float)__ldg(img_h));
        float p1 = __ldg(boxes + roi * 4 + (isx ? 0 : 1)) * scale;
        float p2 = __ldg(boxes + roi * 4 + (isx ? 2 : 3)) * scale;
        float bs = fmaxf(p2 - p1, 1.0f) * (1.0f / 7.0f);
        float P  = p1 + ((float)bin + offs) * bs;

        int lim = isx ? W0 : H0;
        bool valid = (P >= -1.0f) && (P <= (float)lim);
        float Pc = fminf(fmaxf(P, 0.0f), (float)(lim - 1));
        int p0  = (int)Pc;
        int p1i = min(p0 + 1, lim - 1);
        float l  = Pc - (float)p0;
        float w0 = valid ? (1.0f - l) : 0.0f;
        float w1 = valid ? l : 0.0f;

        if (isx) {
            sxo[s][0] = p0 * OPP;    sxo[s][1] = p1i * OPP;
            swx[s][0] = w0;          swx[s][1] = w1;
        } else {
            syo[s][0] = p0 * (W0 * OPP);   syo[s][1] = p1i * (W0 * OPP);
            swy[s][0] = w0 * 0.25f;        swy[s][1] = w1 * 0.25f;
        }
    }
    __syncthreads();

    const uint4* fp = g_fused + slab * 32 + octet;

    int   ya0 = syo[0][0], ya1 = syo[0][1];
    int   yb0 = syo[1][0], yb1 = syo[1][1];
    float wa0 = swy[0][0], wa1 = swy[0][1];
    float wb0 = swy[1][0], wb1 = swy[1][1];

    int s0 = 2 * ow;
    int   x00 = sxo[s0][0],     x01 = sxo[s0][1];
    float u00 = swx[s0][0],     u01 = swx[s0][1];
    int   x10 = sxo[s0 + 1][0], x11 = sxo[s0 + 1][1];
    float u10 = swx[s0 + 1][0], u11 = swx[s0 + 1][1];

    const __half2 hz = __float2half2_rn(0.0f);
    __half2 A[4] = {hz, hz, hz, hz};
    __half2 B[4] = {hz, hz, hz, hz};

    // ---- phase A: sub-sample 0 (x00/x01), 8 batched loads ----
    {
        __half2 k0 = __float2half2_rn(wa0 * u00);
        __half2 k1 = __float2half2_rn(wa1 * u00);
        __half2 k2 = __float2half2_rn(wb0 * u00);
        __half2 k3 = __float2half2_rn(wb1 * u00);
        __half2 k4 = __float2half2_rn(wa0 * u01);
        __half2 k5 = __float2half2_rn(wa1 * u01);
        __half2 k6 = __float2half2_rn(wb0 * u01);
        __half2 k7 = __float2half2_rn(wb1 * u01);
        uint4 t0 = __ldg(fp + ya0 + x00);
        uint4 t1 = __ldg(fp + ya1 + x00);
        uint4 t2 = __ldg(fp + yb0 + x00);
        uint4 t3 = __ldg(fp + yb1 + x00);
        uint4 t4 = __ldg(fp + ya0 + x01);
        uint4 t5 = __ldg(fp + ya1 + x01);
        uint4 t6 = __ldg(fp + yb0 + x01);
        uint4 t7 = __ldg(fp + yb1 + x01);
        FMA8(t0, k0, A) FMA8(t1, k1, A) FMA8(t2, k2, A) FMA8(t3, k3, A)
        FMA8(t4, k4, A) FMA8(t5, k5, A) FMA8(t6, k6, A) FMA8(t7, k7, A)
    }
    // ---- phase B: sub-sample 1 (x10/x11), 8 batched loads ----
    {
        __half2 k0 = __float2half2_rn(wa0 * u10);
        __half2 k1 = __float2half2_rn(wa1 * u10);
        __half2 k2 = __float2half2_rn(wb0 * u10);
        __half2 k3 = __float2half2_rn(wb1 * u10);
        __half2 k4 = __float2half2_rn(wa0 * u11);
        __half2 k5 = __float2half2_rn(wa1 * u11);
        __half2 k6 = __float2half2_rn(wb0 * u11);
        __half2 k7 = __float2half2_rn(wb1 * u11);
        uint4 t0 = __ldg(fp + ya0 + x10);
        uint4 t1 = __ldg(fp + ya1 + x10);
        uint4 t2 = __ldg(fp + yb0 + x10);
        uint4 t3 = __ldg(fp + yb1 + x10);
        uint4 t4 = __ldg(fp + ya0 + x11);
        uint4 t5 = __ldg(fp + ya1 + x11);
        uint4 t6 = __ldg(fp + yb0 + x11);
        uint4 t7 = __ldg(fp + yb1 + x11);
        FMA8(t0, k0, B) FMA8(t1, k1, B) FMA8(t2, k2, B) FMA8(t3, k3, B)
        FMA8(t4, k4, B) FMA8(t5, k5, B) FMA8(t6, k6, B) FMA8(t7, k7, B)
    }

    __half2 c0 = __hadd2(A[0], B[0]);
    __half2 c1 = __hadd2(A[1], B[1]);
    __half2 c2 = __hadd2(A[2], B[2]);
    __half2 c3 = __hadd2(A[3], B[3]);
    uint4 st;
    st.x = *(unsigned*)&c0;  st.y = *(unsigned*)&c1;
    st.z = *(unsigned*)&c2;  st.w = *(unsigned*)&c3;
    s_out4[ow * 32 + octet] = st;

    __syncthreads();

    // element (c_local, ow) lives at sh[ow*256 + c_local]
    const __half* sh = (const __half*)s_out4;
    float* base = out + ((size_t)roi * C_TOT + slab * 256) * 49 + oh * 7;
#pragma unroll
    for (int i = tid; i < 256 * 7; i += 224) {
        int c = i / 7, owv = i - 7 * c;
        base[(size_t)c * 49 + owv] = __half2float(sh[owv * 256 + c]);
    }
}

// ---------------------------------------------------------------------------
// Launch: 3 independent prep->roi chains on 3 streams (fork-join capture).
// ---------------------------------------------------------------------------
namespace {
struct Aux {
    cudaStream_t s1, s2;
    cudaEvent_t fork, j1, j2;
    Aux() {
        cudaStreamCreateWithFlags(&s1, cudaStreamNonBlocking);
        cudaStreamCreateWithFlags(&s2, cudaStreamNonBlocking);
        cudaEventCreateWithFlags(&fork, cudaEventDisableTiming);
        cudaEventCreateWithFlags(&j1, cudaEventDisableTiming);
        cudaEventCreateWithFlags(&j2, cudaEventDisableTiming);
    }
};
Aux& aux() { static Aux a; return a; }
}

extern "C" void kernel_launch(void* const* d_in, const int* in_sizes, int n_in,
                              void* d_out, int out_size) {
    const float* feat0 = (const float*)d_in[0];
    const float* feat1 = (const float*)d_in[1];
    const float* feat2 = (const float*)d_in[2];
    const float* boxes = (const float*)d_in[3];
    const int*   img_h = (const int*)d_in[4];
    const int*   img_w = (const int*)d_in[5];
    float* out = (float*)d_out;

    int N = in_sizes[3] / 4;
    Aux& a = aux();

    // fork from default (capture-origin) stream
    cudaEventRecord(a.fork, 0);
    cudaStreamWaitEvent(a.s1, a.fork, 0);
    cudaStreamWaitEvent(a.s2, a.fork, 0);

    // chain 0 on default stream
    prep0_kernel<<<dim3(10, 200, 4), 256>>>(feat0);
    roi_slab_kernel<<<dim3(N, 7), 224>>>(boxes, img_h, img_w, out, 0);

    // chain 1 on s1
    prep1_kernel<<<dim3(5, 100, 4), 256, 0, a.s1>>>(feat1);
    roi_slab_kernel<<<dim3(N, 7), 224, 0, a.s1>>>(boxes, img_h, img_w, out, 1);

    // chain 2 on s2
    prep2_kernel<<<dim3(5, 100, 4), 256, 0, a.s2>>>(feat2);
    roi_slab_kernel<<<dim3(N, 7), 224, 0, a.s2>>>(boxes, img_h, img_w, out, 2);

    // join back to default stream
    cudaEventRecord(a.j1, a.s1);
    cudaEventRecord(a.j2, a.s2);
    cudaStreamWaitEvent(0, a.j1, 0);
    cudaStreamWaitEvent(0, a.j2, 0);
}